// round 5
// baseline (speedup 1.0000x reference)
#include <cuda_runtime.h>
#include <cstdint>

// GCNConv: out[dst] += feat[src] * w   (edge_dst sorted ascending)
// feat: [N=50000, 64] f32 (12.8 MB -> L2-resident), edge_weight: [E] f32.
// edge_src/edge_dst: declared int64 in the reference, but JAX x64 is disabled
// by default, so the actual device buffers are int32 (R2's illegal-access when
// reading them as int64 corroborates this). Read as int32; bounds-guard
// indices so a wrong dtype guess degrades to rel_err, not a crash.
//
// Design:
//  - Block of 256 threads (8 warps) owns 512 consecutive edges.
//  - Stage (src, dst, w) into smem with coalesced loads.
//  - Each warp processes 64 edges; lane l owns feature columns {2l, 2l+1}.
//  - Sorted dst => long same-dst runs (E/N ~ 25): accumulate in registers,
//    flush via atomicAdd only on run boundary (~2-3 flushes per 64 edges).

#define N_NODES 50000
#define D_FEAT 64
#define EPW 64
#define WARPS_PER_BLOCK 8
#define EPB (EPW * WARPS_PER_BLOCK)  // 512 edges per block

__device__ __forceinline__ void flush_run(float* __restrict__ out, int dst,
                                          int col, float2& acc) {
    if ((unsigned)dst < N_NODES) {
        float* p = out + (size_t)dst * D_FEAT + col;
        atomicAdd(p + 0, acc.x);
        atomicAdd(p + 1, acc.y);
    }
    acc.x = 0.0f;
    acc.y = 0.0f;
}

__global__ __launch_bounds__(256) void gcn_gather_scatter(
    const float* __restrict__ feat,
    const float* __restrict__ ew,
    const int* __restrict__ esrc,
    const int* __restrict__ edst,
    float* __restrict__ out,
    int E) {

    __shared__ int   s_src[EPB];
    __shared__ int   s_dst[EPB];
    __shared__ float s_w[EPB];

    const int blockE0 = blockIdx.x * EPB;
    const int nLocal  = min(EPB, E - blockE0);   // edges owned by this block

    // Coalesced metadata stage.
    for (int i = threadIdx.x; i < nLocal; i += blockDim.x) {
        const int e = blockE0 + i;
        s_src[i] = esrc[e];
        s_dst[i] = edst[e];
        s_w[i]   = ew[e];
    }
    __syncthreads();

    const int warp = threadIdx.x >> 5;
    const int lane = threadIdx.x & 31;

    const int l0 = warp * EPW;            // local edge index within block
    if (l0 >= nLocal) return;
    const int l1 = min(l0 + EPW, nLocal);

    const int col = 2 * lane;

    float2 acc = make_float2(0.0f, 0.0f);
    int cur = s_dst[l0];

    #pragma unroll 4
    for (int i = l0; i < l1; ++i) {
        const int d = s_dst[i];
        if (d != cur) {
            flush_run(out, cur, col, acc);
            cur = d;
        }
        const int   s = s_src[i];
        const float w = s_w[i];
        if ((unsigned)s < N_NODES) {
            const float2 f = *reinterpret_cast<const float2*>(feat + (size_t)s * D_FEAT + col);
            acc.x = fmaf(f.x, w, acc.x);
            acc.y = fmaf(f.y, w, acc.y);
        }
    }
    flush_run(out, cur, col, acc);
}

extern "C" void kernel_launch(void* const* d_in, const int* in_sizes, int n_in,
                              void* d_out, int out_size) {
    const float* feat = (const float*)d_in[0];
    const float* ew   = (const float*)d_in[1];
    const int*   esrc = (const int*)d_in[2];
    const int*   edst = (const int*)d_in[3];
    float*       out  = (float*)d_out;

    const int E = in_sizes[1];  // edge_weight element count

    // d_out is poisoned; zero before accumulation (graph-capturable memset).
    cudaMemsetAsync(d_out, 0, (size_t)out_size * sizeof(float), 0);

    const int blocks = (E + EPB - 1) / EPB;
    gcn_gather_scatter<<<blocks, 256>>>(feat, ew, esrc, edst, out, E);
}

// round 9
// speedup vs baseline: 1.0181x; 1.0181x over previous
#include <cuda_runtime.h>
#include <cstdint>

// GCNConv: out[dst] += feat[src] * w   (edge_dst sorted ascending)
// feat: [N=50000, 64] f32 (L2-resident), indices are int32 (JAX x64 disabled).
//
// R5 measured 39.7us: L1tex 61%, issue 67% => instruction-bound, not BW-bound.
// This design (unmeasured resubmit): half-warp per edge + float4 gather +
// packed metadata.
//  - Each 16-lane half-warp owns one edge at a time; lane hl owns cols 4hl..4hl+3.
//  - One LDG.128 serves 2 edges per warp-instruction (was 1 LDG.64 per edge).
//  - Metadata: (src, w) packed int2 (LDS.64) + dst (LDS.32) => 1 LDS/edge (was 3).
//  - Halves process disjoint contiguous 32-edge ranges so sorted-dst register
//    run accumulation is preserved; flush via atomicAdd on run boundary.

#define N_NODES 50000
#define D_FEAT 64
#define EPW 64                 // edges per warp
#define HALF_E (EPW / 2)       // 32 edges per half-warp
#define WARPS_PER_BLOCK 8
#define EPB (EPW * WARPS_PER_BLOCK)  // 512 edges per block

__device__ __forceinline__ void flush_run(float* __restrict__ out, int dst,
                                          int col, float4& acc) {
    if ((unsigned)dst < N_NODES) {
        float* p = out + (size_t)dst * D_FEAT + col;
        atomicAdd(p + 0, acc.x);
        atomicAdd(p + 1, acc.y);
        atomicAdd(p + 2, acc.z);
        atomicAdd(p + 3, acc.w);
    }
    acc.x = 0.0f; acc.y = 0.0f; acc.z = 0.0f; acc.w = 0.0f;
}

__global__ __launch_bounds__(256) void gcn_gather_scatter(
    const float* __restrict__ feat,
    const float* __restrict__ ew,
    const int* __restrict__ esrc,
    const int* __restrict__ edst,
    float* __restrict__ out,
    int E) {

    __shared__ int2 s_sw[EPB];   // (src, w bits)
    __shared__ int  s_dst[EPB];

    const int blockE0 = blockIdx.x * EPB;
    const int nLocal  = min(EPB, E - blockE0);

    // Coalesced metadata stage.
    #pragma unroll 2
    for (int i = threadIdx.x; i < nLocal; i += blockDim.x) {
        const int e = blockE0 + i;
        s_sw[i]  = make_int2(esrc[e], __float_as_int(ew[e]));
        s_dst[i] = edst[e];
    }
    __syncthreads();

    const int warp = threadIdx.x >> 5;
    const int lane = threadIdx.x & 31;
    const int half = lane >> 4;          // 0 or 1
    const int hl   = lane & 15;          // lane within half-warp
    const int col  = hl * 4;             // 4 columns per lane

    const int base = warp * EPW + half * HALF_E;  // this half's first local edge
    if (base >= nLocal) return;
    const int cnt = min(HALF_E, nLocal - base);

    float4 acc = make_float4(0.0f, 0.0f, 0.0f, 0.0f);
    int cur = s_dst[base];

    #pragma unroll 4
    for (int j = 0; j < cnt; ++j) {
        const int i = base + j;
        const int d = s_dst[i];
        if (d != cur) {
            flush_run(out, cur, col, acc);
            cur = d;
        }
        const int2  sw = s_sw[i];
        const int   s  = sw.x;
        const float w  = __int_as_float(sw.y);
        if ((unsigned)s < N_NODES) {
            const float4 f =
                *reinterpret_cast<const float4*>(feat + (size_t)s * D_FEAT + col);
            acc.x = fmaf(f.x, w, acc.x);
            acc.y = fmaf(f.y, w, acc.y);
            acc.z = fmaf(f.z, w, acc.z);
            acc.w = fmaf(f.w, w, acc.w);
        }
    }
    flush_run(out, cur, col, acc);
}

extern "C" void kernel_launch(void* const* d_in, const int* in_sizes, int n_in,
                              void* d_out, int out_size) {
    const float* feat = (const float*)d_in[0];
    const float* ew   = (const float*)d_in[1];
    const int*   esrc = (const int*)d_in[2];
    const int*   edst = (const int*)d_in[3];
    float*       out  = (float*)d_out;

    const int E = in_sizes[1];  // edge_weight element count

    // d_out is poisoned; zero before accumulation (graph-capturable memset).
    cudaMemsetAsync(d_out, 0, (size_t)out_size * sizeof(float), 0);

    const int blocks = (E + EPB - 1) / EPB;
    gcn_gather_scatter<<<blocks, 256>>>(feat, ew, esrc, edst, out, E);
}

// round 13
// speedup vs baseline: 1.1832x; 1.1622x over previous
#include <cuda_runtime.h>
#include <cstdint>

// GCNConv: out[dst] += feat[src] * w   (edge_dst sorted ascending)
// feat: [N=50000, 64] f32, indices int32 (confirmed by two passing runs).
//
// R9 measured 36.5us with all pipes <=53% => latency-exposure bound: the
// dst-compare branch between iterations serialized the feat gathers (MLP~1).
// This (unmeasured resubmit): explicit 4-edge chunking. Each trip loads 4
// edges' metadata and issues 4 independent LDG.128 gathers BEFORE any branch,
// then flushes/accumulates on register data. MLP_eff ~4 => load latency /4.
//  - 16-lane half-warp owns an edge; lane hl owns cols 4hl..4hl+3 (float4).
//  - Sorted dst => register run accumulation, atomicAdd only on run boundary.

#define N_NODES 50000
#define D_FEAT 64
#define EPW 64                 // edges per warp
#define HALF_E (EPW / 2)       // 32 edges per half-warp
#define WARPS_PER_BLOCK 8
#define EPB (EPW * WARPS_PER_BLOCK)  // 512 edges per block

__device__ __forceinline__ void flush_run(float* __restrict__ out, int dst,
                                          int col, float4& acc) {
    float* p = out + (size_t)dst * D_FEAT + col;
    atomicAdd(p + 0, acc.x);
    atomicAdd(p + 1, acc.y);
    atomicAdd(p + 2, acc.z);
    atomicAdd(p + 3, acc.w);
    acc.x = 0.0f; acc.y = 0.0f; acc.z = 0.0f; acc.w = 0.0f;
}

__device__ __forceinline__ void accum(float4& acc, const float4 f, const float w) {
    acc.x = fmaf(f.x, w, acc.x);
    acc.y = fmaf(f.y, w, acc.y);
    acc.z = fmaf(f.z, w, acc.z);
    acc.w = fmaf(f.w, w, acc.w);
}

__global__ __launch_bounds__(256) void gcn_gather_scatter(
    const float* __restrict__ feat,
    const float* __restrict__ ew,
    const int* __restrict__ esrc,
    const int* __restrict__ edst,
    float* __restrict__ out,
    int E) {

    __shared__ int2 s_sw[EPB];   // (src, w bits)
    __shared__ int  s_dst[EPB];

    const int blockE0 = blockIdx.x * EPB;
    const int nLocal  = min(EPB, E - blockE0);

    // Coalesced metadata stage.
    for (int i = threadIdx.x; i < nLocal; i += blockDim.x) {
        const int e = blockE0 + i;
        s_sw[i]  = make_int2(esrc[e], __float_as_int(ew[e]));
        s_dst[i] = edst[e];
    }
    __syncthreads();

    const int warp = threadIdx.x >> 5;
    const int lane = threadIdx.x & 31;
    const int half = lane >> 4;
    const int hl   = lane & 15;
    const int col  = hl * 4;

    const int base = warp * EPW + half * HALF_E;
    if (base >= nLocal) return;
    const int cnt = min(HALF_E, nLocal - base);

    float4 acc = make_float4(0.0f, 0.0f, 0.0f, 0.0f);
    int cur = s_dst[base];

    int j = 0;
    // Main: 4 edges per trip; all loads issued before any branch.
    for (; j + 4 <= cnt; j += 4) {
        const int i = base + j;
        const int2 sw0 = s_sw[i + 0];
        const int2 sw1 = s_sw[i + 1];
        const int2 sw2 = s_sw[i + 2];
        const int2 sw3 = s_sw[i + 3];
        const int  d0  = s_dst[i + 0];
        const int  d1  = s_dst[i + 1];
        const int  d2  = s_dst[i + 2];
        const int  d3  = s_dst[i + 3];
        // 4 independent gathers -> MLP 4.
        const float4 f0 = *reinterpret_cast<const float4*>(feat + (size_t)sw0.x * D_FEAT + col);
        const float4 f1 = *reinterpret_cast<const float4*>(feat + (size_t)sw1.x * D_FEAT + col);
        const float4 f2 = *reinterpret_cast<const float4*>(feat + (size_t)sw2.x * D_FEAT + col);
        const float4 f3 = *reinterpret_cast<const float4*>(feat + (size_t)sw3.x * D_FEAT + col);

        if (d0 != cur) { flush_run(out, cur, col, acc); cur = d0; }
        accum(acc, f0, __int_as_float(sw0.y));
        if (d1 != cur) { flush_run(out, cur, col, acc); cur = d1; }
        accum(acc, f1, __int_as_float(sw1.y));
        if (d2 != cur) { flush_run(out, cur, col, acc); cur = d2; }
        accum(acc, f2, __int_as_float(sw2.y));
        if (d3 != cur) { flush_run(out, cur, col, acc); cur = d3; }
        accum(acc, f3, __int_as_float(sw3.y));
    }
    // Tail.
    for (; j < cnt; ++j) {
        const int i = base + j;
        const int2 sw = s_sw[i];
        const int  d  = s_dst[i];
        const float4 f = *reinterpret_cast<const float4*>(feat + (size_t)sw.x * D_FEAT + col);
        if (d != cur) { flush_run(out, cur, col, acc); cur = d; }
        accum(acc, f, __int_as_float(sw.y));
    }
    flush_run(out, cur, col, acc);
}

extern "C" void kernel_launch(void* const* d_in, const int* in_sizes, int n_in,
                              void* d_out, int out_size) {
    const float* feat = (const float*)d_in[0];
    const float* ew   = (const float*)d_in[1];
    const int*   esrc = (const int*)d_in[2];
    const int*   edst = (const int*)d_in[3];
    float*       out  = (float*)d_out;

    const int E = in_sizes[1];  // edge_weight element count

    // d_out is poisoned; zero before accumulation (graph-capturable memset).
    cudaMemsetAsync(d_out, 0, (size_t)out_size * sizeof(float), 0);

    const int blocks = (E + EPB - 1) / EPB;
    gcn_gather_scatter<<<blocks, 256>>>(feat, ew, esrc, edst, out, E);
}